// round 8
// baseline (speedup 1.0000x reference)
#include <cuda_runtime.h>
#include <stdint.h>

#define NW      12
#define DIM     4096
#define THREADS 256

typedef unsigned long long u64;

// ---------------------------------------------------------------------------
// Host-side GF(2) machinery.
// CNOT chain acts as index relabel p -> M p. We store amplitudes in the
// q = M p basis, where every layer-1 gate is a standard bit-stride gate:
// wire w pairs along bit (11-w) of q, branch = that bit.
// Measurement sign masks become rows of M (since M^2 M^-1 = M).
// Layer-1 RY gates use the tan factorization RY = cos(th) * [1,-t;t,1];
// the global prod(cos)^2 is folded into the measurement weight table.
// ---------------------------------------------------------------------------

struct CircuitMasks {
    int minv_col[12];   // bit-space columns of M^-1 (for init: p = Minv q)
    int mrow[12];       // bit-space rows of M (for measurement weights)
};

static inline int wire2bits(unsigned wiremask) {
    int m = 0;
    for (int v = 0; v < NW; v++)
        if ((wiremask >> v) & 1) m |= 1 << (11 - v);
    return m;
}

static void compute_masks(CircuitMasks* cm) {
    unsigned M[NW];
    for (int w = 0; w < NW; w++) M[w] = 1u << w;
    for (int w = 0; w < NW - 1; w++) M[w + 1] ^= M[w];
    M[0] ^= M[NW - 1];

    unsigned A[NW], Inv[NW];
    for (int i = 0; i < NW; i++) { A[i] = M[i]; Inv[i] = 1u << i; }
    for (int col = 0; col < NW; col++) {
        int piv = -1;
        for (int r = col; r < NW; r++)
            if ((A[r] >> col) & 1) { piv = r; break; }
        unsigned ta = A[col]; A[col] = A[piv]; A[piv] = ta;
        unsigned ti = Inv[col]; Inv[col] = Inv[piv]; Inv[piv] = ti;
        for (int r = 0; r < NW; r++)
            if (r != col && ((A[r] >> col) & 1)) { A[r] ^= A[col]; Inv[r] ^= Inv[col]; }
    }
    unsigned colw[NW];
    for (int w = 0; w < NW; w++) {
        unsigned c = 0;
        for (int v = 0; v < NW; v++)
            if ((Inv[v] >> w) & 1) c |= 1u << v;
        colw[w] = c;
    }

    for (int j = 0; j < NW; j++) cm->minv_col[j] = wire2bits(colw[11 - j]);
    for (int w = 0; w < NW; w++) cm->mrow[w] = wire2bits(M[w]);
}

// ---------------------------------------------------------------------------
// Device
// ---------------------------------------------------------------------------

__device__ float g_weight[DIM];

// weight = (sum_w sign_w(q) head_w) * prod_w cos^2(0.5*theta2_w)
__global__ void weight_kernel(const float* __restrict__ head_w,
                              const float* __restrict__ params,
                              CircuitMasks cm) {
    int q = blockIdx.x * blockDim.x + threadIdx.x;
    if (q >= DIM) return;
    float acc = 0.f;
#pragma unroll
    for (int w = 0; w < NW; w++) {
        int par = __popc(q & cm.mrow[w]) & 1;
        acc += par ? -head_w[w] : head_w[w];
    }
    float C = 1.f;
#pragma unroll
    for (int w = 0; w < NW; w++)
        C *= cosf(0.5f * params[2 * NW + w * 2 + 0]);   // params[1][w][0]
    g_weight[q] = acc * C * C;
}

// packed f32x2 helpers (Blackwell FFMA2 path)
__device__ __forceinline__ u64 pack2(float a, float b) {
    u64 r; asm("mov.b64 %0, {%1, %2};" : "=l"(r) : "f"(a), "f"(b)); return r;
}
__device__ __forceinline__ u64 ffma2(u64 a, u64 b, u64 c) {
    u64 d; asm("fma.rn.f32x2 %0, %1, %2, %3;" : "=l"(d) : "l"(a), "l"(b), "l"(c)); return d;
}
__device__ __forceinline__ float2 u2f(u64 a) {
    float2 f; asm("mov.b64 {%0, %1}, %2;" : "=f"(f.x), "=f"(f.y) : "l"(a)); return f;
}

__global__ __launch_bounds__(THREADS, 6) void qsim_kernel(
    const float* __restrict__ state_batch,
    const float* __restrict__ params,
    const float* __restrict__ head_b,
    float* __restrict__ out,
    CircuitMasks cm) {
    __shared__ u64    s[DIM];
    __shared__ float2 f0[NW], f1[NW];     // per-wire product-state factors
    __shared__ float2 clo[64], chi[64];   // complex product tables (physical p space)
    __shared__ float  gt[NW];             // layer-1 RY tan(theta) per wire
    __shared__ int    pr[16];             // Minv applied to low-4-bit nibbles
    __shared__ float  red[8];

    const int tid = threadIdx.x;
    const int b = blockIdx.x;

    // --- per-wire angles: RZ(phi) RY(theta + angle) |0>, layer-1 RY tan
    if (tid < NW) {
        int w = tid;
        float ang = state_batch[(size_t)b * DIM + w];
        float th = 0.5f * (ang + params[w * 2 + 0]);     // params[0][w][0]
        float ph = 0.5f * params[w * 2 + 1];             // params[0][w][1]
        float sh, ch_, sp, cp;
        __sincosf(th, &sh, &ch_);
        __sincosf(ph, &sp, &cp);
        f0[w] = make_float2(cp * ch_, -sp * ch_);
        f1[w] = make_float2(cp * sh, sp * sh);
        float t2 = 0.5f * params[2 * NW + w * 2 + 0];    // params[1][w][0]
        float s2, c2;
        __sincosf(t2, &s2, &c2);
        gt[w] = s2 / c2;                                 // tan; cos folded into weight
        // (layer-1 RZ dropped: diagonal before a basis permutation + |.|^2)
    }
    if (tid < 16) {
        int r = tid, p = 0;
        if (r & 1) p ^= cm.minv_col[0];
        if (r & 2) p ^= cm.minv_col[1];
        if (r & 4) p ^= cm.minv_col[2];
        if (r & 8) p ^= cm.minv_col[3];
        pr[r] = p;
    }
    __syncthreads();

    // --- product tables in physical space: bit j of p <-> wire (11-j)
    if (tid < 128) {
        int m = tid & 63;
        bool hi = tid >= 64;
        float2 acc = make_float2(1.f, 0.f);
#pragma unroll
        for (int j = 0; j < 6; j++) {
            int bit = (m >> j) & 1;
            int w = hi ? (5 - j) : (11 - j);
            float2 f = bit ? f1[w] : f0[w];
            acc = make_float2(acc.x * f.x - acc.y * f.y,
                              acc.x * f.y + acc.y * f.x);
        }
        if (hi) chi[m] = acc; else clo[m] = acc;
    }
    __syncthreads();

    // --- init 16 amplitudes straight into registers (mapping1: q = (tid<<4)|r)
    int pb = 0;
#pragma unroll
    for (int i = 0; i < 8; i++)
        if ((tid >> i) & 1) pb ^= cm.minv_col[i + 4];

    u64 v[16];
#pragma unroll
    for (int r = 0; r < 16; r++) {
        int p = pb ^ pr[r];
        float2 lo = clo[p & 63], hi = chi[p >> 6];
        v[r] = pack2(fmaf(hi.x, lo.x, -hi.y * lo.y),
                     fmaf(hi.x, lo.y,  hi.y * lo.x));
    }

    // tan-form gate on register bit bp: v0' = v0 - t v1 ; v1' = t v0 + v1
#define APPLY_BIT(bp, wire) {                                           \
        float t_ = gt[wire];                                            \
        u64 t2_ = pack2(t_, t_), nt2_ = pack2(-t_, -t_);                \
        _Pragma("unroll")                                               \
        for (int r = 0; r < 16; r++) if (!(r & (1 << bp))) {            \
            int r1 = r | (1 << bp);                                     \
            u64 a_ = v[r], d_ = v[r1];                                  \
            v[r]  = ffma2(nt2_, d_, a_);                                \
            v[r1] = ffma2(t2_,  a_, d_);                                \
        }                                                               \
    }

    // --- phase 1: q bits 0..3 in regs -> wires 11,10,9,8
    APPLY_BIT(0, 11); APPLY_BIT(1, 10); APPLY_BIT(2, 9); APPLY_BIT(3, 8);

    const int tx = tid & 15;

    // transpose 1: write mapping1 (phys = (t<<4) | (r^tx))
#pragma unroll
    for (int r = 0; r < 16; r++)
        s[(tid << 4) | (r ^ tx)] = v[r];
    __syncthreads();

    // --- phase 2: read mapping2 (regs = q bits 4..7)
    const int base2 = ((tid >> 4) << 8);
#pragma unroll
    for (int r = 0; r < 16; r++)
        v[r] = s[base2 | (r << 4) | (tx ^ r)];

    // wires 7,6,5,4
    APPLY_BIT(0, 7); APPLY_BIT(1, 6); APPLY_BIT(2, 5); APPLY_BIT(3, 4);

    // write back to the SAME slots this thread read -> no sync needed before
#pragma unroll
    for (int r = 0; r < 16; r++)
        s[base2 | (r << 4) | (tx ^ r)] = v[r];
    __syncthreads();

    // --- phase 3: read mapping3 (regs = q bits 8..11)
    const int thi = tid & 0xF0;
    const int swz3 = tx ^ (tid >> 4);
#pragma unroll
    for (int r = 0; r < 16; r++)
        v[r] = s[(r << 8) | thi | swz3];

    // wires 3,2,1,0
    APPLY_BIT(0, 3); APPLY_BIT(1, 2); APPLY_BIT(2, 1); APPLY_BIT(3, 0);

    // --- measurement: weight table (q space, rows of M + prod cos^2 folded in)
    float acc = 0.f;
#pragma unroll
    for (int r = 0; r < 16; r++) {
        float2 a = u2f(v[r]);
        acc = fmaf(fmaf(a.x, a.x, a.y * a.y), g_weight[(r << 8) | tid], acc);
    }
#pragma unroll
    for (int o = 16; o > 0; o >>= 1)
        acc += __shfl_xor_sync(0xffffffffu, acc, o);
    if ((tid & 31) == 0) red[tid >> 5] = acc;
    __syncthreads();
    if (tid == 0) {
        float t = 0.f;
#pragma unroll
        for (int i = 0; i < 8; i++) t += red[i];
        out[b] = t + head_b[0];
    }
#undef APPLY_BIT
}

// ---------------------------------------------------------------------------

extern "C" void kernel_launch(void* const* d_in, const int* in_sizes, int n_in,
                              void* d_out, int out_size) {
    const float* state_batch = (const float*)d_in[0];
    const float* params      = (const float*)d_in[1];
    const float* head_w      = (const float*)d_in[2];
    const float* head_b      = (const float*)d_in[3];
    float* out = (float*)d_out;

    CircuitMasks cm;
    compute_masks(&cm);

    weight_kernel<<<16, 256>>>(head_w, params, cm);
    qsim_kernel<<<out_size, THREADS>>>(state_batch, params, head_b, out, cm);
}

// round 9
// speedup vs baseline: 1.4824x; 1.4824x over previous
#include <cuda_runtime.h>
#include <stdint.h>

#define NW      12
#define DIM     4096
#define THREADS 256

typedef unsigned long long u64;

// ---------------------------------------------------------------------------
// Host-side GF(2) machinery.
// CNOT chain acts as index relabel p -> M p. We store amplitudes in the
// q = M p basis, where every layer-1 gate is a standard bit-stride gate:
// wire w pairs along bit (11-w) of q, branch = that bit.
// Measurement sign masks are rows of M (since M^2 M^-1 = M); for the fixed
// chain these are 0x7FF, 0xC00, 0xE00, 0xF00, 0xF80..0xFFF, whose high
// nibbles are only {7,12,14,15} -> the head projection is 4 Walsh-Hadamard
// coefficients of the per-thread probability vector (computed in-kernel;
// no weight table / second kernel needed).
// Layer-1 RY gates use the tan factorization RY = cos(th) * [1,-t;t,1];
// the global prod(cos)^2 is applied at the end.
// ---------------------------------------------------------------------------

struct CircuitMasks {
    int minv_col[12];   // bit-space columns of M^-1 (for init: p = Minv q)
};

static inline int wire2bits(unsigned wiremask) {
    int m = 0;
    for (int v = 0; v < NW; v++)
        if ((wiremask >> v) & 1) m |= 1 << (11 - v);
    return m;
}

static void compute_masks(CircuitMasks* cm) {
    unsigned M[NW];
    for (int w = 0; w < NW; w++) M[w] = 1u << w;
    for (int w = 0; w < NW - 1; w++) M[w + 1] ^= M[w];
    M[0] ^= M[NW - 1];

    unsigned A[NW], Inv[NW];
    for (int i = 0; i < NW; i++) { A[i] = M[i]; Inv[i] = 1u << i; }
    for (int col = 0; col < NW; col++) {
        int piv = -1;
        for (int r = col; r < NW; r++)
            if ((A[r] >> col) & 1) { piv = r; break; }
        unsigned ta = A[col]; A[col] = A[piv]; A[piv] = ta;
        unsigned ti = Inv[col]; Inv[col] = Inv[piv]; Inv[piv] = ti;
        for (int r = 0; r < NW; r++)
            if (r != col && ((A[r] >> col) & 1)) { A[r] ^= A[col]; Inv[r] ^= Inv[col]; }
    }
    unsigned colw[NW];
    for (int w = 0; w < NW; w++) {
        unsigned c = 0;
        for (int v = 0; v < NW; v++)
            if ((Inv[v] >> w) & 1) c |= 1u << v;
        colw[w] = c;
    }

    for (int j = 0; j < NW; j++) cm->minv_col[j] = wire2bits(colw[11 - j]);
}

// ---------------------------------------------------------------------------
// Device
// ---------------------------------------------------------------------------

// packed f32x2 helpers (Blackwell FFMA2 path)
__device__ __forceinline__ u64 pack2(float a, float b) {
    u64 r; asm("mov.b64 %0, {%1, %2};" : "=l"(r) : "f"(a), "f"(b)); return r;
}
__device__ __forceinline__ u64 ffma2(u64 a, u64 b, u64 c) {
    u64 d; asm("fma.rn.f32x2 %0, %1, %2, %3;" : "=l"(d) : "l"(a), "l"(b), "l"(c)); return d;
}
__device__ __forceinline__ float2 u2f(u64 a) {
    float2 f; asm("mov.b64 {%0, %1}, %2;" : "=f"(f.x), "=f"(f.y) : "l"(a)); return f;
}

__global__ __launch_bounds__(THREADS, 5) void qsim_kernel(
    const float* __restrict__ state_batch,
    const float* __restrict__ params,
    const float* __restrict__ head_w,
    const float* __restrict__ head_b,
    float* __restrict__ out,
    CircuitMasks cm) {
    __shared__ u64    s[DIM];
    __shared__ float2 f0[NW], f1[NW];     // per-wire product-state factors
    __shared__ float2 clo[64], chi[64];   // complex product tables (physical p space)
    __shared__ float  gt[NW];             // layer-1 RY tan(theta) per wire
    __shared__ float  cw2[NW];            // layer-1 RY cos^2 per wire
    __shared__ float  shw[NW];            // head_w
    __shared__ float  sCsq;               // prod cos^2
    __shared__ int    pr[16];             // Minv applied to low-4-bit nibbles
    __shared__ float  red[8];

    const int tid = threadIdx.x;
    const int b = blockIdx.x;

    // --- per-wire angles: RZ(phi) RY(theta + angle) |0>, layer-1 RY tan
    if (tid < NW) {
        int w = tid;
        float ang = state_batch[(size_t)b * DIM + w];
        float th = 0.5f * (ang + params[w * 2 + 0]);     // params[0][w][0]
        float ph = 0.5f * params[w * 2 + 1];             // params[0][w][1]
        float sh, ch_, sp, cp;
        __sincosf(th, &sh, &ch_);
        __sincosf(ph, &sp, &cp);
        f0[w] = make_float2(cp * ch_, -sp * ch_);
        f1[w] = make_float2(cp * sh, sp * sh);
        float t2 = 0.5f * params[2 * NW + w * 2 + 0];    // params[1][w][0]
        float s2, c2;
        __sincosf(t2, &s2, &c2);
        gt[w] = s2 / c2;                                 // tan; cos applied at end
        cw2[w] = c2 * c2;
        shw[w] = head_w[w];
        // (layer-1 RZ dropped: diagonal before a basis permutation + |.|^2)
    }
    if (tid < 16) {
        int r = tid, p = 0;
        if (r & 1) p ^= cm.minv_col[0];
        if (r & 2) p ^= cm.minv_col[1];
        if (r & 4) p ^= cm.minv_col[2];
        if (r & 8) p ^= cm.minv_col[3];
        pr[r] = p;
    }
    __syncthreads();

    // --- product tables in physical space: bit j of p <-> wire (11-j)
    if (tid < 128) {
        int m = tid & 63;
        bool hi = tid >= 64;
        float2 acc = make_float2(1.f, 0.f);
#pragma unroll
        for (int j = 0; j < 6; j++) {
            int bit = (m >> j) & 1;
            int w = hi ? (5 - j) : (11 - j);
            float2 f = bit ? f1[w] : f0[w];
            acc = make_float2(acc.x * f.x - acc.y * f.y,
                              acc.x * f.y + acc.y * f.x);
        }
        if (hi) chi[m] = acc; else clo[m] = acc;
    }
    if (tid == 0) {
        float P = 1.f;
#pragma unroll
        for (int w = 0; w < NW; w++) P *= cw2[w];
        sCsq = P;
    }
    __syncthreads();

    // --- init 16 amplitudes straight into registers (mapping1: q = (tid<<4)|r)
    int pb = 0;
#pragma unroll
    for (int i = 0; i < 8; i++)
        if ((tid >> i) & 1) pb ^= cm.minv_col[i + 4];

    u64 v[16];
#pragma unroll
    for (int r = 0; r < 16; r++) {
        int p = pb ^ pr[r];
        float2 lo = clo[p & 63], hi = chi[p >> 6];
        v[r] = pack2(fmaf(hi.x, lo.x, -hi.y * lo.y),
                     fmaf(hi.x, lo.y,  hi.y * lo.x));
    }

    // tan-form gate on register bit bp: v0' = v0 - t v1 ; v1' = t v0 + v1
#define APPLY_BIT(bp, wire) {                                           \
        float t_ = gt[wire];                                            \
        u64 t2_ = pack2(t_, t_), nt2_ = pack2(-t_, -t_);                \
        _Pragma("unroll")                                               \
        for (int r = 0; r < 16; r++) if (!(r & (1 << bp))) {            \
            int r1 = r | (1 << bp);                                     \
            u64 a_ = v[r], d_ = v[r1];                                  \
            v[r]  = ffma2(nt2_, d_, a_);                                \
            v[r1] = ffma2(t2_,  a_, d_);                                \
        }                                                               \
    }

    // --- phase 1: q bits 0..3 in regs -> wires 11,10,9,8
    APPLY_BIT(0, 11); APPLY_BIT(1, 10); APPLY_BIT(2, 9); APPLY_BIT(3, 8);

    const int tx = tid & 15;

    // transpose 1: write mapping1 (phys = (t<<4) | (r^tx))
#pragma unroll
    for (int r = 0; r < 16; r++)
        s[(tid << 4) | (r ^ tx)] = v[r];
    __syncthreads();

    // --- phase 2: read mapping2 (regs = q bits 4..7)
    const int base2 = ((tid >> 4) << 8);
#pragma unroll
    for (int r = 0; r < 16; r++)
        v[r] = s[base2 | (r << 4) | (tx ^ r)];

    // wires 7,6,5,4
    APPLY_BIT(0, 7); APPLY_BIT(1, 6); APPLY_BIT(2, 5); APPLY_BIT(3, 4);

    // write back to the SAME slots this thread read -> no sync needed before
#pragma unroll
    for (int r = 0; r < 16; r++)
        s[base2 | (r << 4) | (tx ^ r)] = v[r];
    __syncthreads();

    // --- phase 3: read mapping3 (regs = q bits 8..11; q = (r<<8)|tid)
    const int thi = tid & 0xF0;
    const int swz3 = tx ^ (tid >> 4);
#pragma unroll
    for (int r = 0; r < 16; r++)
        v[r] = s[(r << 8) | thi | swz3];

    // wires 3,2,1,0
    APPLY_BIT(0, 3); APPLY_BIT(1, 2); APPLY_BIT(2, 1); APPLY_BIT(3, 0);

    // --- measurement via Walsh-Hadamard over the 16 per-thread probabilities.
    // weight((r<<8)|tid) = sum_w (-1)^{par(r&m_w)} (-1)^{par(tid&l_w)} hw_w,
    // with (m_w,l_w): w0:(7,0xFF) w1:(12,0) w2:(14,0) w3:(15,0)
    //                 w4..w11:(15, 0x80,0xC0,0xE0,0xF0,0xF8,0xFC,0xFE,0xFF)
    float prob[16];
#pragma unroll
    for (int r = 0; r < 16; r++) {
        float2 a = u2f(v[r]);
        prob[r] = fmaf(a.x, a.x, a.y * a.y);
    }
    // fast WHT over the 4 register bits (unused outputs dead-coded)
#pragma unroll
    for (int k = 0; k < 4; k++) {
        int st = 1 << k;
#pragma unroll
        for (int r = 0; r < 16; r++) if (!(r & st)) {
            float a0 = prob[r], b0 = prob[r | st];
            prob[r] = a0 + b0;
            prob[r | st] = a0 - b0;
        }
    }
    // per-thread tid-parity signs: cumulative parity of top bits of tid
    int b7 = (tid >> 7) & 1, b6 = (tid >> 6) & 1, b5 = (tid >> 5) & 1,
        b4 = (tid >> 4) & 1, b3 = (tid >> 3) & 1, b2 = (tid >> 2) & 1,
        b1 = (tid >> 1) & 1, b0 = tid & 1;
    int s4 = b7, s5 = s4 ^ b6, s6 = s5 ^ b5, s7 = s6 ^ b4,
        s8 = s7 ^ b3, s9 = s8 ^ b2, s10 = s9 ^ b1, s11 = s10 ^ b0;
    float D = shw[3];
    D += s4  ? -shw[4]  : shw[4];
    D += s5  ? -shw[5]  : shw[5];
    D += s6  ? -shw[6]  : shw[6];
    D += s7  ? -shw[7]  : shw[7];
    D += s8  ? -shw[8]  : shw[8];
    D += s9  ? -shw[9]  : shw[9];
    D += s10 ? -shw[10] : shw[10];
    D += s11 ? -shw[11] : shw[11];
    float A = s11 ? -shw[0] : shw[0];    // l_0 = 0xFF -> full parity of tid

    float acc = A * prob[7];
    acc = fmaf(shw[1], prob[12], acc);
    acc = fmaf(shw[2], prob[14], acc);
    acc = fmaf(D,      prob[15], acc);

#pragma unroll
    for (int o = 16; o > 0; o >>= 1)
        acc += __shfl_xor_sync(0xffffffffu, acc, o);
    if ((tid & 31) == 0) red[tid >> 5] = acc;
    __syncthreads();
    if (tid == 0) {
        float t = 0.f;
#pragma unroll
        for (int i = 0; i < 8; i++) t += red[i];
        out[b] = fmaf(t, sCsq, head_b[0]);
    }
#undef APPLY_BIT
}

// ---------------------------------------------------------------------------

extern "C" void kernel_launch(void* const* d_in, const int* in_sizes, int n_in,
                              void* d_out, int out_size) {
    const float* state_batch = (const float*)d_in[0];
    const float* params      = (const float*)d_in[1];
    const float* head_w      = (const float*)d_in[2];
    const float* head_b      = (const float*)d_in[3];
    float* out = (float*)d_out;

    CircuitMasks cm;
    compute_masks(&cm);

    qsim_kernel<<<out_size, THREADS>>>(state_batch, params, head_w, head_b, out, cm);
}

// round 10
// speedup vs baseline: 1.8465x; 1.2456x over previous
#include <cuda_runtime.h>
#include <stdint.h>

#define NW      12
#define DIM     4096
#define THREADS 256

typedef unsigned long long u64;

// ---------------------------------------------------------------------------
// GF(2) machinery. CNOT chain = index relabel p -> M p; we store amplitudes
// in q = M p basis where each layer-1 gate is a single-bit-stride gate
// (wire w <-> q bit 11-w). Measurement masks are rows of M; their
// {bit0,bit9,bit10,bit11} parts are {7,12,14,15} in phase-3 register space
// -> Walsh-Hadamard epilogue. M^-1 columns for q bits 1..4 live in p's low
// 6 bits -> chi factor constant per thread in phase 1 (init = 17 LDS).
// Layer-1 RY = cos * [1,-t;t,1]; prod(cos)^2 applied at the end.
// ---------------------------------------------------------------------------

struct CircuitMasks {
    int minv_col[12];   // bit-space columns of M^-1
    int pr16[16];       // XOR combos of minv_col[1..4] (low-6-bit masks)
};

static inline int wire2bits(unsigned wiremask) {
    int m = 0;
    for (int v = 0; v < NW; v++)
        if ((wiremask >> v) & 1) m |= 1 << (11 - v);
    return m;
}

static void compute_masks(CircuitMasks* cm) {
    unsigned M[NW];
    for (int w = 0; w < NW; w++) M[w] = 1u << w;
    for (int w = 0; w < NW - 1; w++) M[w + 1] ^= M[w];
    M[0] ^= M[NW - 1];

    unsigned A[NW], Inv[NW];
    for (int i = 0; i < NW; i++) { A[i] = M[i]; Inv[i] = 1u << i; }
    for (int col = 0; col < NW; col++) {
        int piv = -1;
        for (int r = col; r < NW; r++)
            if ((A[r] >> col) & 1) { piv = r; break; }
        unsigned ta = A[col]; A[col] = A[piv]; A[piv] = ta;
        unsigned ti = Inv[col]; Inv[col] = Inv[piv]; Inv[piv] = ti;
        for (int r = 0; r < NW; r++)
            if (r != col && ((A[r] >> col) & 1)) { A[r] ^= A[col]; Inv[r] ^= Inv[col]; }
    }
    unsigned colw[NW];
    for (int w = 0; w < NW; w++) {
        unsigned c = 0;
        for (int v = 0; v < NW; v++)
            if ((Inv[v] >> w) & 1) c |= 1u << v;
        colw[w] = c;
    }

    for (int j = 0; j < NW; j++) cm->minv_col[j] = wire2bits(colw[11 - j]);
    for (int r = 0; r < 16; r++) {
        int p = 0;
        if (r & 1) p ^= cm->minv_col[1];
        if (r & 2) p ^= cm->minv_col[2];
        if (r & 4) p ^= cm->minv_col[3];
        if (r & 8) p ^= cm->minv_col[4];
        cm->pr16[r] = p;   // guaranteed subset of 0x1F for this fixed circuit
    }
}

// ---------------------------------------------------------------------------
// Device
// ---------------------------------------------------------------------------

// packed f32x2 helpers (Blackwell FFMA2 path)
__device__ __forceinline__ u64 pack2(float a, float b) {
    u64 r; asm("mov.b64 %0, {%1, %2};" : "=l"(r) : "f"(a), "f"(b)); return r;
}
__device__ __forceinline__ u64 ffma2(u64 a, u64 b, u64 c) {
    u64 d; asm("fma.rn.f32x2 %0, %1, %2, %3;" : "=l"(d) : "l"(a), "l"(b), "l"(c)); return d;
}
__device__ __forceinline__ float2 u2f(u64 a) {
    float2 f; asm("mov.b64 {%0, %1}, %2;" : "=f"(f.x), "=f"(f.y) : "l"(a)); return f;
}

// GF(2)-linear state swizzle: conflict-free for all three phase patterns.
__device__ __forceinline__ int sw(int q) {
    return q ^ ((q >> 5) & 0xE) ^ ((q >> 4) & 1);
}
// table-entry swizzle: puts index bits 4,5 into bank bits
__device__ __forceinline__ int tsw(int m) { return m ^ ((m >> 3) & 6); }

__global__ __launch_bounds__(THREADS, 5) void qsim_kernel(
    const float* __restrict__ state_batch,
    const float* __restrict__ params,
    const float* __restrict__ head_w,
    const float* __restrict__ head_b,
    float* __restrict__ out,
    CircuitMasks cm) {
    __shared__ u64    s[DIM];
    __shared__ float2 f0[NW], f1[NW];     // per-wire product-state factors
    __shared__ float2 clo[64], chi[64];   // product tables (tsw-swizzled slots)
    __shared__ float  gt[NW];             // layer-1 RY tan per wire
    __shared__ float  cw2[NW];            // layer-1 RY cos^2 per wire
    __shared__ float  shw[NW];            // head_w
    __shared__ float  red[8];

    const int tid = threadIdx.x;
    const int b = blockIdx.x;

    // --- per-wire angles
    if (tid < NW) {
        int w = tid;
        float ang = state_batch[(size_t)b * DIM + w];
        float th = 0.5f * (ang + params[w * 2 + 0]);
        float ph = 0.5f * params[w * 2 + 1];
        float sh, ch_, sp, cp;
        __sincosf(th, &sh, &ch_);
        __sincosf(ph, &sp, &cp);
        f0[w] = make_float2(cp * ch_, -sp * ch_);
        f1[w] = make_float2(cp * sh, sp * sh);
        float t2 = 0.5f * params[2 * NW + w * 2 + 0];
        float s2, c2;
        __sincosf(t2, &s2, &c2);
        gt[w] = s2 / c2;
        cw2[w] = c2 * c2;
        shw[w] = head_w[w];
    }
    __syncthreads();

    // --- product tables (physical p space; bit j of p <-> wire 11-j)
    if (tid < 128) {
        int m = tid & 63;
        bool hi = tid >= 64;
        float2 acc = make_float2(1.f, 0.f);
#pragma unroll
        for (int j = 0; j < 6; j++) {
            int bit = (m >> j) & 1;
            int w = hi ? (5 - j) : (11 - j);
            float2 f = bit ? f1[w] : f0[w];
            acc = make_float2(acc.x * f.x - acc.y * f.y,
                              acc.x * f.y + acc.y * f.x);
        }
        if (hi) chi[tsw(m)] = acc; else clo[tsw(m)] = acc;
    }
    __syncthreads();

    // --- init 16 amplitudes (phase-1 order: regs = q bits 1..4)
    // q: bit0 = tid&1, bits 5..11 = tid bits 1..7
    int pb = 0;
    if (tid & 1) pb ^= cm.minv_col[0];
#pragma unroll
    for (int i = 1; i < 8; i++)
        if ((tid >> i) & 1) pb ^= cm.minv_col[i + 4];

    const float2 hf = chi[tsw((pb >> 6) & 63)];   // constant per thread
    u64 v[16];
#pragma unroll
    for (int r = 0; r < 16; r++) {
        int li = (pb ^ cm.pr16[r]) & 63;
        float2 lo = clo[tsw(li)];
        v[r] = pack2(fmaf(hf.x, lo.x, -hf.y * lo.y),
                     fmaf(hf.x, lo.y,  hf.y * lo.x));
    }

    // tan-form gate on register bit bp: v0' = v0 - t v1 ; v1' = t v0 + v1
#define APPLY_BIT(bp, wire) {                                           \
        float t_ = gt[wire];                                            \
        u64 t2_ = pack2(t_, t_), nt2_ = pack2(-t_, -t_);                \
        _Pragma("unroll")                                               \
        for (int r = 0; r < 16; r++) if (!(r & (1 << bp))) {            \
            int r1 = r | (1 << bp);                                     \
            u64 a_ = v[r], d_ = v[r1];                                  \
            v[r]  = ffma2(nt2_, d_, a_);                                \
            v[r1] = ffma2(t2_,  a_, d_);                                \
        }                                                               \
    }

    // --- phase 1: q bits 1..4 -> wires 10,9,8,7
    APPLY_BIT(0, 10); APPLY_BIT(1, 9); APPLY_BIT(2, 8); APPLY_BIT(3, 7);

    const int sb1 = sw((tid & 1) | ((tid >> 1) << 5));
#pragma unroll
    for (int r = 0; r < 16; r++)
        s[sb1 ^ sw(r << 1)] = v[r];
    __syncthreads();

    // --- phase 2: regs = q bits 5..8 -> wires 6,5,4,3
    const int sb2 = sw((tid & 31) | ((tid >> 5) << 9));
#pragma unroll
    for (int r = 0; r < 16; r++)
        v[r] = s[sb2 ^ sw(r << 5)];

    APPLY_BIT(0, 6); APPLY_BIT(1, 5); APPLY_BIT(2, 4); APPLY_BIT(3, 3);

#pragma unroll
    for (int r = 0; r < 16; r++)
        s[sb2 ^ sw(r << 5)] = v[r];
    __syncthreads();

    // --- phase 3: regs = q bits {0,9,10,11} -> wires 11,2,1,0
    const int sb3 = sw(tid << 1);
#pragma unroll
    for (int r = 0; r < 16; r++)
        v[r] = s[sb3 ^ sw((r & 1) | ((r >> 1) << 9))];

    APPLY_BIT(0, 11); APPLY_BIT(1, 2); APPLY_BIT(2, 1); APPLY_BIT(3, 0);

    // --- Walsh-Hadamard measurement over the 16 per-thread probabilities.
    // reg bit 0 <-> q0, bits 1..3 <-> q9..q11. Needed outputs m = 7,12,14,15.
    float prob[16];
#pragma unroll
    for (int r = 0; r < 16; r++) {
        float2 a = u2f(v[r]);
        prob[r] = fmaf(a.x, a.x, a.y * a.y);
    }
#pragma unroll
    for (int k = 0; k < 4; k++) {
        int st = 1 << k;
#pragma unroll
        for (int r = 0; r < 16; r++) if (!(r & st)) {
            float a0 = prob[r], b0 = prob[r | st];
            prob[r] = a0 + b0;
            prob[r | st] = a0 - b0;
        }
    }
    // tid bits t_i <-> q bits i+1. Cumulative parities from the top bit.
    int b7 = (tid >> 7) & 1, b6 = (tid >> 6) & 1, b5 = (tid >> 5) & 1,
        b4 = (tid >> 4) & 1, b3 = (tid >> 3) & 1, b2 = (tid >> 2) & 1,
        b1 = (tid >> 1) & 1, b0 = tid & 1;
    int p7 = b7, p6 = p7 ^ b6, p5 = p6 ^ b5, p4 = p5 ^ b4,
        p3 = p4 ^ b3, p2 = p3 ^ b2, p1 = p2 ^ b1, p0 = p1 ^ b0;
    // WHT[14]: hw2 (no tid sign) + hw3..hw10 with masks 0x80..0xFF
    float W14 = shw[2];
    W14 += p7 ? -shw[3]  : shw[3];
    W14 += p6 ? -shw[4]  : shw[4];
    W14 += p5 ? -shw[5]  : shw[5];
    W14 += p4 ? -shw[6]  : shw[6];
    W14 += p3 ? -shw[7]  : shw[7];
    W14 += p2 ? -shw[8]  : shw[8];
    W14 += p1 ? -shw[9]  : shw[9];
    W14 += p0 ? -shw[10] : shw[10];
    float A7  = p0 ? -shw[0]  : shw[0];   // w0: full tid parity
    float A15 = p0 ? -shw[11] : shw[11];  // w11: full tid parity

    float acc = A7 * prob[7];
    acc = fmaf(shw[1], prob[12], acc);
    acc = fmaf(W14,    prob[14], acc);
    acc = fmaf(A15,    prob[15], acc);

#pragma unroll
    for (int o = 16; o > 0; o >>= 1)
        acc += __shfl_xor_sync(0xffffffffu, acc, o);
    if ((tid & 31) == 0) red[tid >> 5] = acc;
    __syncthreads();
    if (tid == 0) {
        float t = 0.f;
#pragma unroll
        for (int i = 0; i < 8; i++) t += red[i];
        float Csq = 1.f;
#pragma unroll
        for (int w = 0; w < NW; w++) Csq *= cw2[w];
        out[b] = fmaf(t, Csq, head_b[0]);
    }
#undef APPLY_BIT
}

// ---------------------------------------------------------------------------

extern "C" void kernel_launch(void* const* d_in, const int* in_sizes, int n_in,
                              void* d_out, int out_size) {
    const float* state_batch = (const float*)d_in[0];
    const float* params      = (const float*)d_in[1];
    const float* head_w      = (const float*)d_in[2];
    const float* head_b      = (const float*)d_in[3];
    float* out = (float*)d_out;

    CircuitMasks cm;
    compute_masks(&cm);

    qsim_kernel<<<out_size, THREADS>>>(state_batch, params, head_w, head_b, out, cm);
}